// round 16
// baseline (speedup 1.0000x reference)
#include <cuda_runtime.h>
#include <cuda_fp16.h>

#define NN 100000
#define EE 1600000
#define GG 2048
#define HD 64
#define SCAN_B 1024
#define SCAN_G ((NN + SCAN_B - 1) / SCAN_B)   // 98
#define SPLIT 50048                            // 782 * 64

// ---------------- scratch ----------------
__device__ float    g_hA[NN * HD];      // fp32 final activations (fc input)
__device__ __half   g_hB[NN * HD];      // fp16 inter-layer activations (GEMM input)
__device__ __half   g_hwA[NN * HD];     // fp16 features buffer A (GCN, GAT2)
__device__ __half   g_hwB[NN * HD];     // fp16 features buffer B (GAT1)
__device__ float    g_dinv[NN];
__device__ float    g_as1[NN], g_ad1[NN];
__device__ float    g_as2[NN], g_ad2[NN];
__device__ int      g_cnt[NN];          // stays zeroed between runs
__device__ int      g_rs[NN + 1];
__device__ int      g_cur[NN];
__device__ int      g_bsum[SCAN_G], g_boff[SCAN_G];
__device__ int      g_tick;             // stays zeroed between runs
__device__ volatile int g_flag;         // release flag; reset by k_cnt each run
__device__ uint2    c_pack[EE];         // (src, half2(es1,es2)) CSR-ordered
__device__ float    g_v[32];

__device__ __forceinline__ float lrelu(float a) { return (a > 0.f) ? a : 0.2f * a; }
__device__ __forceinline__ __half* hwbuf(int b) { return b ? g_hwB : g_hwA; }
__device__ __forceinline__ float*  asbuf(int b) { return b ? g_as2 : g_as1; }
__device__ __forceinline__ float*  adbuf(int b) { return b ? g_ad2 : g_ad1; }

// ---------------- setup ----------------

__global__ void k_cnt(const int4* __restrict__ dst4,
                      const float* __restrict__ We1, const float* __restrict__ ae1,
                      const float* __restrict__ We2, const float* __restrict__ ae2) {
    int i = blockIdx.x * blockDim.x + threadIdx.x;
    if (blockIdx.x == 0 && threadIdx.x < 32) {
        int t = threadIdx.x;
        const float* We = (t < 16) ? We1 : We2;
        const float* ae = (t < 16) ? ae1 : ae2;
        int j = t & 15;
        float s = 0.f;
        #pragma unroll 8
        for (int c = 0; c < HD; c++) s += We[j * HD + c] * ae[c];
        g_v[t] = s;
    }
    if (blockIdx.x == 0 && threadIdx.x == 32) g_flag = 0;   // arm scan release
    if (i < EE / 4) {
        int4 d = dst4[i];
        atomicAdd(&g_cnt[d.x], 1);
        atomicAdd(&g_cnt[d.y], 1);
        atomicAdd(&g_cnt[d.z], 1);
        atomicAdd(&g_cnt[d.w], 1);
    }
}

// fused scan (R14)
__global__ void k_scan() {
    __shared__ int wsum[32];
    __shared__ int is_last;
    int t = threadIdx.x;
    int i = blockIdx.x * SCAN_B + t;
    int v = (i < NN) ? g_cnt[i] : 0;
    int lane = t & 31, w = t >> 5;
    int x = v;
    #pragma unroll
    for (int off = 1; off < 32; off <<= 1) {
        int y = __shfl_up_sync(0xffffffffu, x, off);
        if (lane >= off) x += y;
    }
    if (lane == 31) wsum[w] = x;
    __syncthreads();
    if (w == 0) {
        int s = wsum[lane];
        #pragma unroll
        for (int off = 1; off < 32; off <<= 1) {
            int y = __shfl_up_sync(0xffffffffu, s, off);
            if (lane >= off) s += y;
        }
        wsum[lane] = s;
    }
    __syncthreads();
    int incl = x + ((w > 0) ? wsum[w - 1] : 0);
    if (t == SCAN_B - 1) g_bsum[blockIdx.x] = incl;
    __threadfence();
    __syncthreads();
    if (t == 0) is_last = (atomicAdd(&g_tick, 1) == SCAN_G - 1) ? 1 : 0;
    __syncthreads();
    if (is_last) {
        if (t < 32) {
            __threadfence();
            int base = lane * 4;
            int v0 = (base + 0 < SCAN_G) ? g_bsum[base + 0] : 0;
            int v1 = (base + 1 < SCAN_G) ? g_bsum[base + 1] : 0;
            int v2 = (base + 2 < SCAN_G) ? g_bsum[base + 2] : 0;
            int v3 = (base + 3 < SCAN_G) ? g_bsum[base + 3] : 0;
            int e1 = v0, e2 = v0 + v1, e3 = v0 + v1 + v2;
            int tot = e3 + v3;
            int xx = tot;
            #pragma unroll
            for (int off = 1; off < 32; off <<= 1) {
                int y = __shfl_up_sync(0xffffffffu, xx, off);
                if (lane >= off) xx += y;
            }
            int excl = xx - tot;
            if (base + 0 < SCAN_G) g_boff[base + 0] = excl;
            if (base + 1 < SCAN_G) g_boff[base + 1] = excl + e1;
            if (base + 2 < SCAN_G) g_boff[base + 2] = excl + e2;
            if (base + 3 < SCAN_G) g_boff[base + 3] = excl + e3;
            __threadfence();
            if (lane == 0) { g_tick = 0; g_flag = 1; }
        }
        __syncthreads();
    } else {
        if (t == 0) { while (g_flag == 0) { } }
        __syncthreads();
        __threadfence();
    }
    if (i < NN) {
        int rs = incl - v + g_boff[blockIdx.x];
        g_rs[i] = rs;
        g_cur[i] = rs;
        g_dinv[i] = rsqrtf((float)(v + 1));
        g_cnt[i] = 0;
    }
    if (i == 0) g_rs[NN] = EE;
}

// 4 edges/thread scatter (R13)
__global__ void k_scatter(const float* __restrict__ ea,
                          const int* __restrict__ src, const int* __restrict__ dst) {
    int i = blockIdx.x * blockDim.x + threadIdx.x;
    const int Q = EE / 4;
    if (i >= Q) return;
    float s1[4], s2[4];
    int sv[4], dv[4];
    #pragma unroll
    for (int e = 0; e < 4; e++) {
        int idx = i + e * Q;
        sv[e] = src[idx];
        dv[e] = dst[idx];
        const float4* p = (const float4*)(ea + (size_t)idx * 16);
        float a1 = 0.f, a2 = 0.f;
        #pragma unroll
        for (int k = 0; k < 4; k++) {
            float4 q = p[k];
            a1 += q.x * g_v[4*k] + q.y * g_v[4*k+1] + q.z * g_v[4*k+2] + q.w * g_v[4*k+3];
            a2 += q.x * g_v[16+4*k] + q.y * g_v[16+4*k+1] + q.z * g_v[16+4*k+2] + q.w * g_v[16+4*k+3];
        }
        s1[e] = a1; s2[e] = a2;
    }
    #pragma unroll
    for (int e = 0; e < 4; e++) {
        int pos = atomicAdd(&g_cur[dv[e]], 1);
        __half2 h = __floats2half2_rn(s1[e], s2[e]);
        uint2 pk;
        pk.x = (unsigned)sv[e];
        pk.y = *reinterpret_cast<unsigned*>(&h);
        c_pack[pos] = pk;
    }
}

// ---------------- tensor-core GEMM ----------------
// DINV=1: rows pre-scaled by dinv (GCN). ATT=1: epilogue a_s/a_d into asbuf/adbuf(attBuf).
// Output features -> hwbuf(dstBuf).
template <int KD, int ATT, int DINV>
__global__ void k_gemm(const float* __restrict__ Xext, const float* __restrict__ W,
                       const float* __restrict__ att_s, const float* __restrict__ att_d,
                       int useInternal, int nodeBase, int dstBuf, int attBuf) {
    __shared__ __half Xs[64][KD + 8];
    __shared__ __half Ws[KD][72];
    __shared__ float sred[64], dred[64];
    int tid = threadIdx.x;
    int node0 = nodeBase + blockIdx.x * 64;
    __half* hw = hwbuf(dstBuf);

    if (useInternal) {
        for (int i = tid; i < 64 * (KD / 2); i += 256) {
            int r = i / (KD / 2), c2 = i % (KD / 2);
            __half2 v = (node0 + r < NN)
                ? ((const __half2*)(g_hB + (size_t)(node0 + r) * KD))[c2]
                : __floats2half2_rn(0.f, 0.f);
            *((__half2*)&Xs[r][c2 * 2]) = v;
        }
    } else {
        for (int i = tid; i < 64 * KD; i += 256) {
            int r = i / KD, k = i % KD;
            float v = (node0 + r < NN) ? Xext[(size_t)(node0 + r) * KD + k] : 0.f;
            Xs[r][k] = __float2half(v);
        }
    }
    for (int i = tid; i < KD * 64; i += 256) {
        int k = i >> 6, n = i & 63;
        Ws[k][n] = __float2half(W[k * 64 + n]);
    }
    if (ATT && tid < 64) { sred[tid] = 0.f; dred[tid] = 0.f; }
    __syncthreads();

    int wid  = tid >> 5;
    int lane = tid & 31;
    int rt = wid >> 1;
    int ch = wid & 1;
    int g  = lane >> 2;
    int t2 = (lane & 3) * 2;
    int row0 = rt * 16;

    float c[4][4];
    #pragma unroll
    for (int nt = 0; nt < 4; nt++)
        #pragma unroll
        for (int q = 0; q < 4; q++) c[nt][q] = 0.f;

    #pragma unroll
    for (int ks = 0; ks < KD / 16; ks++) {
        int k0 = ks * 16;
        unsigned a0 = *(const unsigned*)&Xs[row0 + g    ][k0 + t2];
        unsigned a1 = *(const unsigned*)&Xs[row0 + g + 8][k0 + t2];
        unsigned a2 = *(const unsigned*)&Xs[row0 + g    ][k0 + t2 + 8];
        unsigned a3 = *(const unsigned*)&Xs[row0 + g + 8][k0 + t2 + 8];
        #pragma unroll
        for (int nt = 0; nt < 4; nt++) {
            int n0 = ch * 32 + nt * 8 + g;
            __half2 b0h = __halves2half2(Ws[k0 + t2    ][n0], Ws[k0 + t2 + 1][n0]);
            __half2 b1h = __halves2half2(Ws[k0 + t2 + 8][n0], Ws[k0 + t2 + 9][n0]);
            unsigned b0 = *reinterpret_cast<unsigned*>(&b0h);
            unsigned b1 = *reinterpret_cast<unsigned*>(&b1h);
            asm volatile(
                "mma.sync.aligned.m16n8k16.row.col.f32.f16.f16.f32 "
                "{%0,%1,%2,%3}, {%4,%5,%6,%7}, {%8,%9}, {%0,%1,%2,%3};"
                : "+f"(c[nt][0]), "+f"(c[nt][1]), "+f"(c[nt][2]), "+f"(c[nt][3])
                : "r"(a0), "r"(a1), "r"(a2), "r"(a3), "r"(b0), "r"(b1));
        }
    }

    int rowA = node0 + row0 + g;
    int rowB = rowA + 8;
    float scA = 1.f, scB = 1.f;
    if (DINV) {
        scA = (rowA < NN) ? g_dinv[rowA] : 1.f;
        scB = (rowB < NN) ? g_dinv[rowB] : 1.f;
    }
    #pragma unroll
    for (int nt = 0; nt < 4; nt++) {
        int col = ch * 32 + nt * 8 + t2;
        if (rowA < NN)
            *(__half2*)&hw[(size_t)rowA * 64 + col] = __floats2half2_rn(c[nt][0] * scA, c[nt][1] * scA);
        if (rowB < NN)
            *(__half2*)&hw[(size_t)rowB * 64 + col] = __floats2half2_rn(c[nt][2] * scB, c[nt][3] * scB);
    }

    if (ATT) {
        float pAs = 0.f, pAd = 0.f, pBs = 0.f, pBd = 0.f;
        #pragma unroll
        for (int nt = 0; nt < 4; nt++) {
            int col = ch * 32 + nt * 8 + t2;
            float s0 = att_s[col], s1v = att_s[col + 1];
            float d0 = att_d[col], d1v = att_d[col + 1];
            pAs += c[nt][0] * s0 + c[nt][1] * s1v;
            pAd += c[nt][0] * d0 + c[nt][1] * d1v;
            pBs += c[nt][2] * s0 + c[nt][3] * s1v;
            pBd += c[nt][2] * d0 + c[nt][3] * d1v;
        }
        #pragma unroll
        for (int o = 1; o < 4; o <<= 1) {
            pAs += __shfl_xor_sync(0xffffffffu, pAs, o);
            pAd += __shfl_xor_sync(0xffffffffu, pAd, o);
            pBs += __shfl_xor_sync(0xffffffffu, pBs, o);
            pBd += __shfl_xor_sync(0xffffffffu, pBd, o);
        }
        if ((lane & 3) == 0) {
            atomicAdd(&sred[row0 + g],     pAs);
            atomicAdd(&dred[row0 + g],     pAd);
            atomicAdd(&sred[row0 + g + 8], pBs);
            atomicAdd(&dred[row0 + g + 8], pBd);
        }
        __syncthreads();
        if (tid < 64 && node0 + tid < NN) {
            asbuf(attBuf)[node0 + tid] = sred[tid];
            adbuf(attBuf)[node0 + tid] = dred[tid];
        }
    }
}

// ---------------- gathers ----------------

__device__ __forceinline__ float2 hwrow(const __half* hw, int s, int lane) {
    __half2 v = *((const __half2*)(hw + (size_t)s * 64) + lane);
    return __half22float2(v);
}

// GCN: rows pre-scaled by dinv -> pure row sum; reads hwbuf(srcBuf)
__global__ void k_gcn_node(const float* __restrict__ b, int base, int srcBuf) {
    int node = base + blockIdx.x * 8 + (threadIdx.x >> 5);
    int lane = threadIdx.x & 31;
    if (node >= NN) return;
    const __half* hw = hwbuf(srcBuf);
    int rs = g_rs[node], re = g_rs[node + 1];
    float a0 = 0.f, a1 = 0.f;
    for (int jb = rs; jb < re; jb += 32) {
        int n = re - jb; if (n > 32) n = 32;
        int s_l = (lane < n) ? (int)c_pack[jb + lane].x : 0;
        #pragma unroll 8
        for (int j = 0; j < n; j++) {
            int s = __shfl_sync(0xffffffffu, s_l, j);
            float2 f = hwrow(hw, s, lane);
            a0 += f.x; a1 += f.y;
        }
    }
    float2 fs = hwrow(hw, node, lane);   // already dinv-scaled
    a0 += fs.x; a1 += fs.y;
    float di = g_dinv[node];
    float2 bb = ((const float2*)b)[lane];
    float ox = fmaxf(a0 * di + bb.x, 0.f);
    float oy = fmaxf(a1 * di + bb.y, 0.f);
    ((__half2*)(g_hB + (size_t)node * 64))[lane] = __floats2half2_rn(ox, oy);
}

// OUT: 0 -> fp16 g_hB, 1 -> fp32 g_hA. reads hwbuf(srcBuf), asbuf/adbuf(attBuf)
template <int LAYER, int OUT>
__global__ void k_gat_node(const float* __restrict__ b, int base, int srcBuf, int attBuf) {
    int node = base + blockIdx.x * 8 + (threadIdx.x >> 5);
    int lane = threadIdx.x & 31;
    if (node >= NN) return;
    const __half* hw = hwbuf(srcBuf);
    const float* asp = asbuf(attBuf);
    float ad_n = adbuf(attBuf)[node];
    int rs = g_rs[node], re = g_rs[node + 1];
    float a0 = 0.f, a1 = 0.f, den_l = 0.f, es_l = 0.f;
    for (int jb = rs; jb < re; jb += 32) {
        int n = re - jb; if (n > 32) n = 32;
        int s_l = 0; float x_l = 0.f;
        if (lane < n) {
            uint2 q = c_pack[jb + lane];
            s_l = (int)q.x;
            __half2 eh = *reinterpret_cast<__half2*>(&q.y);
            float e = (LAYER == 1) ? __low2float(eh) : __high2float(eh);
            x_l = __expf(lrelu(asp[s_l] + ad_n + e));
            den_l += x_l;
            es_l  += e;
        }
        #pragma unroll 8
        for (int j = 0; j < n; j++) {
            int s   = __shfl_sync(0xffffffffu, s_l, j);
            float x = __shfl_sync(0xffffffffu, x_l, j);
            float2 f = hwrow(hw, s, lane);
            a0 += x * f.x; a1 += x * f.y;
        }
    }
    #pragma unroll
    for (int o = 16; o; o >>= 1) {
        den_l += __shfl_xor_sync(0xffffffffu, den_l, o);
        es_l  += __shfl_xor_sync(0xffffffffu, es_l, o);
    }
    float cnt = (float)(re - rs);
    float x = __expf(lrelu(asp[node] + ad_n + es_l / fmaxf(cnt, 1.f)));
    float den = den_l + x;
    float2 fs = hwrow(hw, node, lane);
    a0 += x * fs.x; a1 += x * fs.y;
    float inv = 1.f / den;
    float2 bb = ((const float2*)b)[lane];
    float ox = fmaxf(a0 * inv + bb.x, 0.f);
    float oy = fmaxf(a1 * inv + bb.y, 0.f);
    if (OUT == 0) {
        ((__half2*)(g_hB + (size_t)node * 64))[lane] = __floats2half2_rn(ox, oy);
    } else {
        float2 o; o.x = ox; o.y = oy;
        ((float2*)(g_hA + (size_t)node * 64))[lane] = o;
    }
}

// ---------------- head (R14) ----------------

__global__ void k_fc(const int* __restrict__ batch,
                     const float* __restrict__ W1, const float* __restrict__ b1,
                     const float* __restrict__ W2, const float* __restrict__ b2,
                     float* __restrict__ out) {
    __shared__ float t0[64], t1[64];
    __shared__ int srange[2];
    int g = blockIdx.x, c = threadIdx.x;
    if (c < 2) {
        int target = g + c;
        int lo = 0, hi = NN;
        while (lo < hi) {
            int mid = (lo + hi) >> 1;
            if (batch[mid] < target) lo = mid + 1; else hi = mid;
        }
        srange[c] = lo;
    }
    __syncthreads();
    int ns = srange[0], ne = srange[1];
    float m = -3.402823466e+38f;
    for (int n = ns; n < ne; n++)
        m = fmaxf(m, g_hA[(size_t)n * 64 + c]);
    t0[c] = m;
    __syncthreads();
    float s = 0.f;
    #pragma unroll 8
    for (int k = 0; k < 64; k++) s += t0[k] * W1[k * 64 + c];
    t1[c] = fmaxf(s + b1[c], 0.f);
    __syncthreads();
    float o = 0.f;
    #pragma unroll 8
    for (int k = 0; k < 64; k++) o += t1[k] * W2[k * 64 + c];
    out[g * 64 + c] = o + b2[c];
}

// ---------------- launch ----------------
extern "C" void kernel_launch(void* const* d_in, const int* in_sizes, int n_in,
                              void* d_out, int out_size) {
    const float* x     = (const float*)d_in[0];
    const int*   ei    = (const int*)  d_in[1];
    const float* ea    = (const float*)d_in[2];
    const int*   batch = (const int*)  d_in[3];
    const float* W_gcn = (const float*)d_in[4];
    const float* b_gcn = (const float*)d_in[5];
    const float* W1    = (const float*)d_in[6];
    const float* We1   = (const float*)d_in[7];
    const float* as1   = (const float*)d_in[8];
    const float* ad1   = (const float*)d_in[9];
    const float* ae1   = (const float*)d_in[10];
    const float* b1    = (const float*)d_in[11];
    const float* W2    = (const float*)d_in[12];
    const float* We2   = (const float*)d_in[13];
    const float* as2   = (const float*)d_in[14];
    const float* ad2   = (const float*)d_in[15];
    const float* ae2   = (const float*)d_in[16];
    const float* b2    = (const float*)d_in[17];
    const float* Wf1   = (const float*)d_in[18];
    const float* bf1   = (const float*)d_in[19];
    const float* Wf2   = (const float*)d_in[20];
    const float* bf2   = (const float*)d_in[21];
    float* out = (float*)d_out;

    const int* src = ei;
    const int* dst = ei + EE;

    const int TB = 256;
    const int gGemm  = (NN + 63) / 64;       // 1563
    const int gGemm0 = SPLIT / 64;           // 782
    const int gGemm1 = gGemm - gGemm0;       // 781
    const int gN0    = SPLIT / 8;            // 6256
    const int gN1    = (NN - SPLIT) / 8;     // 6244
    const int gNode  = (NN + 7) / 8;

    cudaStream_t s2;
    cudaEvent_t evScan, evB, evG0, evM0, evG1, evM1;
    cudaStreamCreateWithFlags(&s2, cudaStreamNonBlocking);
    cudaEventCreateWithFlags(&evScan, cudaEventDisableTiming);
    cudaEventCreateWithFlags(&evB,  cudaEventDisableTiming);
    cudaEventCreateWithFlags(&evG0, cudaEventDisableTiming);
    cudaEventCreateWithFlags(&evM0, cudaEventDisableTiming);
    cudaEventCreateWithFlags(&evG1, cudaEventDisableTiming);
    cudaEventCreateWithFlags(&evM1, cudaEventDisableTiming);

    // CSR build on main; GCN GEMM (needs dinv) on side, hidden under scatter
    k_cnt<<<(EE / 4 + TB - 1) / TB, TB>>>((const int4*)dst, We1, ae1, We2, ae2);
    k_scan<<<SCAN_G, SCAN_B>>>();
    cudaEventRecord(evScan, 0);
    cudaStreamWaitEvent(s2, evScan, 0);
    k_gemm<128, 0, 1><<<gGemm, TB, 0, s2>>>(x, W_gcn, nullptr, nullptr, 0, 0, /*dst=A*/0, 0);
    cudaEventRecord(evB, s2);
    k_scatter<<<(EE / 4 + TB - 1) / TB, TB>>>(ea, src, dst);
    cudaStreamWaitEvent(0, evB, 0);

    // GCN gather (reads hwA) half0 -> fork GAT1 GEMM(half0, writes hwB/as1) || gather half1
    k_gcn_node<<<gN0, TB>>>(b_gcn, 0, /*src=A*/0);
    cudaEventRecord(evG0, 0);
    cudaStreamWaitEvent(s2, evG0, 0);
    k_gemm<64, 1, 0><<<gGemm0, TB, 0, s2>>>(nullptr, W1, as1, ad1, 1, 0, /*dst=B*/1, /*att=1*/0);
    cudaEventRecord(evM0, s2);
    k_gcn_node<<<gN1, TB>>>(b_gcn, SPLIT, 0);
    k_gemm<64, 1, 0><<<gGemm1, TB>>>(nullptr, W1, as1, ad1, 1, SPLIT, 1, 0);
    cudaStreamWaitEvent(0, evM0, 0);

    // GAT1 gather (reads hwB/as1) half0 -> fork GAT2 GEMM(half0, writes hwA/as2) || gather half1
    k_gat_node<1, 0><<<gN0, TB>>>(b1, 0, /*src=B*/1, /*att*/0);
    cudaEventRecord(evG1, 0);
    cudaStreamWaitEvent(s2, evG1, 0);
    k_gemm<64, 1, 0><<<gGemm0, TB, 0, s2>>>(nullptr, W2, as2, ad2, 1, 0, /*dst=A*/0, /*att*/1);
    cudaEventRecord(evM1, s2);
    k_gat_node<1, 0><<<gN1, TB>>>(b1, SPLIT, 1, 0);
    k_gemm<64, 1, 0><<<gGemm1, TB>>>(nullptr, W2, as2, ad2, 1, SPLIT, 0, 1);
    cudaStreamWaitEvent(0, evM1, 0);

    // GAT2 gather (reads hwA/as2, full) + head
    k_gat_node<2, 1><<<gNode, TB>>>(b2, 0, /*src=A*/0, /*att*/1);
    k_fc<<<GG, 64>>>(batch, Wf1, bf1, Wf2, bf2, out);

    cudaStreamDestroy(s2);
    cudaEventDestroy(evScan);
    cudaEventDestroy(evB);
    cudaEventDestroy(evG0);
    cudaEventDestroy(evM0);
    cudaEventDestroy(evG1);
    cudaEventDestroy(evM1);
}

// round 17
// speedup vs baseline: 1.1022x; 1.1022x over previous
#include <cuda_runtime.h>
#include <cuda_fp16.h>

#define NN 100000
#define EE 1600000
#define GG 2048
#define HD 64
#define SCAN_B 1024
#define SCAN_G ((NN + SCAN_B - 1) / SCAN_B)   // 98

// ---------------- scratch ----------------
__device__ float    g_hA[NN * HD];      // fp32 final activations (fc input)
__device__ __half   g_hB[NN * HD];      // fp16 inter-layer activations (GEMM input)
__device__ __half   g_hw[NN * HD];      // fp16 pre-aggregation features
__device__ float    g_dinv[NN];
__device__ float    g_as[NN], g_ad[NN];
__device__ int      g_cnt[NN];          // stays zeroed between runs
__device__ int      g_rs[NN + 1];
__device__ int      g_cur[NN];
__device__ int      g_bsum[SCAN_G], g_boff[SCAN_G];
__device__ int      g_tick;             // stays zeroed between runs
__device__ volatile int g_flag;         // release flag; reset by k_cnt each run
__device__ uint2    c_pack[EE];         // (src, half2(es1,es2)) CSR-ordered
__device__ float    g_v[32];

__device__ __forceinline__ float lrelu(float a) { return (a > 0.f) ? a : 0.2f * a; }

// ---------------- setup ----------------

__global__ void k_cnt(const int4* __restrict__ dst4,
                      const float* __restrict__ We1, const float* __restrict__ ae1,
                      const float* __restrict__ We2, const float* __restrict__ ae2) {
    int i = blockIdx.x * blockDim.x + threadIdx.x;
    if (blockIdx.x == 0 && threadIdx.x < 32) {
        int t = threadIdx.x;
        const float* We = (t < 16) ? We1 : We2;
        const float* ae = (t < 16) ? ae1 : ae2;
        int j = t & 15;
        float s = 0.f;
        #pragma unroll 8
        for (int c = 0; c < HD; c++) s += We[j * HD + c] * ae[c];
        g_v[t] = s;
    }
    if (blockIdx.x == 0 && threadIdx.x == 32) g_flag = 0;   // arm scan release
    if (i < EE / 4) {
        int4 d = dst4[i];
        atomicAdd(&g_cnt[d.x], 1);
        atomicAdd(&g_cnt[d.y], 1);
        atomicAdd(&g_cnt[d.z], 1);
        atomicAdd(&g_cnt[d.w], 1);
    }
}

// fused scan (R14)
__global__ void k_scan() {
    __shared__ int wsum[32];
    __shared__ int is_last;
    int t = threadIdx.x;
    int i = blockIdx.x * SCAN_B + t;
    int v = (i < NN) ? g_cnt[i] : 0;
    int lane = t & 31, w = t >> 5;
    int x = v;
    #pragma unroll
    for (int off = 1; off < 32; off <<= 1) {
        int y = __shfl_up_sync(0xffffffffu, x, off);
        if (lane >= off) x += y;
    }
    if (lane == 31) wsum[w] = x;
    __syncthreads();
    if (w == 0) {
        int s = wsum[lane];
        #pragma unroll
        for (int off = 1; off < 32; off <<= 1) {
            int y = __shfl_up_sync(0xffffffffu, s, off);
            if (lane >= off) s += y;
        }
        wsum[lane] = s;
    }
    __syncthreads();
    int incl = x + ((w > 0) ? wsum[w - 1] : 0);
    if (t == SCAN_B - 1) g_bsum[blockIdx.x] = incl;
    __threadfence();
    __syncthreads();
    if (t == 0) is_last = (atomicAdd(&g_tick, 1) == SCAN_G - 1) ? 1 : 0;
    __syncthreads();
    if (is_last) {
        if (t < 32) {
            __threadfence();
            int base = lane * 4;
            int v0 = (base + 0 < SCAN_G) ? g_bsum[base + 0] : 0;
            int v1 = (base + 1 < SCAN_G) ? g_bsum[base + 1] : 0;
            int v2 = (base + 2 < SCAN_G) ? g_bsum[base + 2] : 0;
            int v3 = (base + 3 < SCAN_G) ? g_bsum[base + 3] : 0;
            int e1 = v0, e2 = v0 + v1, e3 = v0 + v1 + v2;
            int tot = e3 + v3;
            int xx = tot;
            #pragma unroll
            for (int off = 1; off < 32; off <<= 1) {
                int y = __shfl_up_sync(0xffffffffu, xx, off);
                if (lane >= off) xx += y;
            }
            int excl = xx - tot;
            if (base + 0 < SCAN_G) g_boff[base + 0] = excl;
            if (base + 1 < SCAN_G) g_boff[base + 1] = excl + e1;
            if (base + 2 < SCAN_G) g_boff[base + 2] = excl + e2;
            if (base + 3 < SCAN_G) g_boff[base + 3] = excl + e3;
            __threadfence();
            if (lane == 0) { g_tick = 0; g_flag = 1; }
        }
        __syncthreads();
    } else {
        if (t == 0) { while (g_flag == 0) { } }
        __syncthreads();
        __threadfence();
    }
    if (i < NN) {
        int rs = incl - v + g_boff[blockIdx.x];
        g_rs[i] = rs;
        g_cur[i] = rs;
        g_dinv[i] = rsqrtf((float)(v + 1));
        g_cnt[i] = 0;
    }
    if (i == 0) g_rs[NN] = EE;
}

// 4 edges/thread scatter (R13)
__global__ void k_scatter(const float* __restrict__ ea,
                          const int* __restrict__ src, const int* __restrict__ dst) {
    int i = blockIdx.x * blockDim.x + threadIdx.x;
    const int Q = EE / 4;
    if (i >= Q) return;
    float s1[4], s2[4];
    int sv[4], dv[4];
    #pragma unroll
    for (int e = 0; e < 4; e++) {
        int idx = i + e * Q;
        sv[e] = src[idx];
        dv[e] = dst[idx];
        const float4* p = (const float4*)(ea + (size_t)idx * 16);
        float a1 = 0.f, a2 = 0.f;
        #pragma unroll
        for (int k = 0; k < 4; k++) {
            float4 q = p[k];
            a1 += q.x * g_v[4*k] + q.y * g_v[4*k+1] + q.z * g_v[4*k+2] + q.w * g_v[4*k+3];
            a2 += q.x * g_v[16+4*k] + q.y * g_v[16+4*k+1] + q.z * g_v[16+4*k+2] + q.w * g_v[16+4*k+3];
        }
        s1[e] = a1; s2[e] = a2;
    }
    #pragma unroll
    for (int e = 0; e < 4; e++) {
        int pos = atomicAdd(&g_cur[dv[e]], 1);
        __half2 h = __floats2half2_rn(s1[e], s2[e]);
        uint2 pk;
        pk.x = (unsigned)sv[e];
        pk.y = *reinterpret_cast<unsigned*>(&h);
        c_pack[pos] = pk;
    }
}

// ---------------- tensor-core GEMM ----------------
// DINV=1: rows pre-scaled by dinv (GCN).  ATT=1: epilogue a_s/a_d.
template <int KD, int ATT, int DINV>
__global__ void k_gemm(const float* __restrict__ Xext, const float* __restrict__ W,
                       const float* __restrict__ att_s, const float* __restrict__ att_d,
                       int useInternal) {
    __shared__ __half Xs[64][KD + 8];
    __shared__ __half Ws[KD][72];
    __shared__ float sred[64], dred[64];
    int tid = threadIdx.x;
    int node0 = blockIdx.x * 64;

    if (useInternal) {
        for (int i = tid; i < 64 * (KD / 2); i += 256) {
            int r = i / (KD / 2), c2 = i % (KD / 2);
            __half2 v = (node0 + r < NN)
                ? ((const __half2*)(g_hB + (size_t)(node0 + r) * KD))[c2]
                : __floats2half2_rn(0.f, 0.f);
            *((__half2*)&Xs[r][c2 * 2]) = v;
        }
    } else {
        for (int i = tid; i < 64 * KD; i += 256) {
            int r = i / KD, k = i % KD;
            float v = (node0 + r < NN) ? Xext[(size_t)(node0 + r) * KD + k] : 0.f;
            Xs[r][k] = __float2half(v);
        }
    }
    for (int i = tid; i < KD * 64; i += 256) {
        int k = i >> 6, n = i & 63;
        Ws[k][n] = __float2half(W[k * 64 + n]);
    }
    if (ATT && tid < 64) { sred[tid] = 0.f; dred[tid] = 0.f; }
    __syncthreads();

    int wid  = tid >> 5;
    int lane = tid & 31;
    int rt = wid >> 1;
    int ch = wid & 1;
    int g  = lane >> 2;
    int t2 = (lane & 3) * 2;
    int row0 = rt * 16;

    float c[4][4];
    #pragma unroll
    for (int nt = 0; nt < 4; nt++)
        #pragma unroll
        for (int q = 0; q < 4; q++) c[nt][q] = 0.f;

    #pragma unroll
    for (int ks = 0; ks < KD / 16; ks++) {
        int k0 = ks * 16;
        unsigned a0 = *(const unsigned*)&Xs[row0 + g    ][k0 + t2];
        unsigned a1 = *(const unsigned*)&Xs[row0 + g + 8][k0 + t2];
        unsigned a2 = *(const unsigned*)&Xs[row0 + g    ][k0 + t2 + 8];
        unsigned a3 = *(const unsigned*)&Xs[row0 + g + 8][k0 + t2 + 8];
        #pragma unroll
        for (int nt = 0; nt < 4; nt++) {
            int n0 = ch * 32 + nt * 8 + g;
            __half2 b0h = __halves2half2(Ws[k0 + t2    ][n0], Ws[k0 + t2 + 1][n0]);
            __half2 b1h = __halves2half2(Ws[k0 + t2 + 8][n0], Ws[k0 + t2 + 9][n0]);
            unsigned b0 = *reinterpret_cast<unsigned*>(&b0h);
            unsigned b1 = *reinterpret_cast<unsigned*>(&b1h);
            asm volatile(
                "mma.sync.aligned.m16n8k16.row.col.f32.f16.f16.f32 "
                "{%0,%1,%2,%3}, {%4,%5,%6,%7}, {%8,%9}, {%0,%1,%2,%3};"
                : "+f"(c[nt][0]), "+f"(c[nt][1]), "+f"(c[nt][2]), "+f"(c[nt][3])
                : "r"(a0), "r"(a1), "r"(a2), "r"(a3), "r"(b0), "r"(b1));
        }
    }

    int rowA = node0 + row0 + g;
    int rowB = rowA + 8;
    float scA = 1.f, scB = 1.f;
    if (DINV) {
        scA = (rowA < NN) ? g_dinv[rowA] : 1.f;
        scB = (rowB < NN) ? g_dinv[rowB] : 1.f;
    }
    #pragma unroll
    for (int nt = 0; nt < 4; nt++) {
        int col = ch * 32 + nt * 8 + t2;
        if (rowA < NN)
            *(__half2*)&g_hw[(size_t)rowA * 64 + col] = __floats2half2_rn(c[nt][0] * scA, c[nt][1] * scA);
        if (rowB < NN)
            *(__half2*)&g_hw[(size_t)rowB * 64 + col] = __floats2half2_rn(c[nt][2] * scB, c[nt][3] * scB);
    }

    if (ATT) {
        float pAs = 0.f, pAd = 0.f, pBs = 0.f, pBd = 0.f;
        #pragma unroll
        for (int nt = 0; nt < 4; nt++) {
            int col = ch * 32 + nt * 8 + t2;
            float s0 = att_s[col], s1v = att_s[col + 1];
            float d0 = att_d[col], d1v = att_d[col + 1];
            pAs += c[nt][0] * s0 + c[nt][1] * s1v;
            pAd += c[nt][0] * d0 + c[nt][1] * d1v;
            pBs += c[nt][2] * s0 + c[nt][3] * s1v;
            pBd += c[nt][2] * d0 + c[nt][3] * d1v;
        }
        #pragma unroll
        for (int o = 1; o < 4; o <<= 1) {
            pAs += __shfl_xor_sync(0xffffffffu, pAs, o);
            pAd += __shfl_xor_sync(0xffffffffu, pAd, o);
            pBs += __shfl_xor_sync(0xffffffffu, pBs, o);
            pBd += __shfl_xor_sync(0xffffffffu, pBd, o);
        }
        if ((lane & 3) == 0) {
            atomicAdd(&sred[row0 + g],     pAs);
            atomicAdd(&dred[row0 + g],     pAd);
            atomicAdd(&sred[row0 + g + 8], pBs);
            atomicAdd(&dred[row0 + g + 8], pBd);
        }
        __syncthreads();
        if (tid < 64 && node0 + tid < NN) {
            g_as[node0 + tid] = sred[tid];
            g_ad[node0 + tid] = dred[tid];
        }
    }
}

// ---------------- gathers ----------------

__device__ __forceinline__ float2 hwrow(int s, int lane) {
    __half2 v = *((const __half2*)(g_hw + (size_t)s * 64) + lane);
    return __half22float2(v);
}

// GCN: rows pre-scaled by dinv -> pure row sum
__global__ void k_gcn_node(const float* __restrict__ b) {
    int node = blockIdx.x * 8 + (threadIdx.x >> 5);
    int lane = threadIdx.x & 31;
    if (node >= NN) return;
    int rs = g_rs[node], re = g_rs[node + 1];
    float a0 = 0.f, a1 = 0.f;
    for (int jb = rs; jb < re; jb += 32) {
        int n = re - jb; if (n > 32) n = 32;
        int s_l = (lane < n) ? (int)c_pack[jb + lane].x : 0;
        #pragma unroll 8
        for (int j = 0; j < n; j++) {
            int s = __shfl_sync(0xffffffffu, s_l, j);
            float2 f = hwrow(s, lane);
            a0 += f.x; a1 += f.y;
        }
    }
    float2 fs = hwrow(node, lane);   // already dinv-scaled
    a0 += fs.x; a1 += fs.y;
    float di = g_dinv[node];
    float2 bb = ((const float2*)b)[lane];
    float ox = fmaxf(a0 * di + bb.x, 0.f);
    float oy = fmaxf(a1 * di + bb.y, 0.f);
    ((__half2*)(g_hB + (size_t)node * 64))[lane] = __floats2half2_rn(ox, oy);
}

// OUT: 0 -> fp16 g_hB, 1 -> fp32 g_hA
template <int LAYER, int OUT>
__global__ void k_gat_node(const float* __restrict__ b) {
    int node = blockIdx.x * 8 + (threadIdx.x >> 5);
    int lane = threadIdx.x & 31;
    if (node >= NN) return;
    int rs = g_rs[node], re = g_rs[node + 1];
    float ad_n = g_ad[node];
    float a0 = 0.f, a1 = 0.f, den_l = 0.f, es_l = 0.f;
    for (int jb = rs; jb < re; jb += 32) {
        int n = re - jb; if (n > 32) n = 32;
        int s_l = 0; float x_l = 0.f;
        if (lane < n) {
            uint2 q = c_pack[jb + lane];
            s_l = (int)q.x;
            __half2 eh = *reinterpret_cast<__half2*>(&q.y);
            float e = (LAYER == 1) ? __low2float(eh) : __high2float(eh);
            x_l = __expf(lrelu(g_as[s_l] + ad_n + e));
            den_l += x_l;
            es_l  += e;
        }
        #pragma unroll 8
        for (int j = 0; j < n; j++) {
            int s   = __shfl_sync(0xffffffffu, s_l, j);
            float x = __shfl_sync(0xffffffffu, x_l, j);
            float2 f = hwrow(s, lane);
            a0 += x * f.x; a1 += x * f.y;
        }
    }
    #pragma unroll
    for (int o = 16; o; o >>= 1) {
        den_l += __shfl_xor_sync(0xffffffffu, den_l, o);
        es_l  += __shfl_xor_sync(0xffffffffu, es_l, o);
    }
    float cnt = (float)(re - rs);
    float x = __expf(lrelu(g_as[node] + ad_n + es_l / fmaxf(cnt, 1.f)));
    float den = den_l + x;
    float2 fs = hwrow(node, lane);
    a0 += x * fs.x; a1 += x * fs.y;
    float inv = 1.f / den;
    float2 bb = ((const float2*)b)[lane];
    float ox = fmaxf(a0 * inv + bb.x, 0.f);
    float oy = fmaxf(a1 * inv + bb.y, 0.f);
    if (OUT == 0) {
        ((__half2*)(g_hB + (size_t)node * 64))[lane] = __floats2half2_rn(ox, oy);
    } else {
        float2 o; o.x = ox; o.y = oy;
        ((float2*)(g_hA + (size_t)node * 64))[lane] = o;
    }
}

// ---------------- head (R14) ----------------

__global__ void k_fc(const int* __restrict__ batch,
                     const float* __restrict__ W1, const float* __restrict__ b1,
                     const float* __restrict__ W2, const float* __restrict__ b2,
                     float* __restrict__ out) {
    __shared__ float t0[64], t1[64];
    __shared__ int srange[2];
    int g = blockIdx.x, c = threadIdx.x;
    if (c < 2) {
        int target = g + c;
        int lo = 0, hi = NN;
        while (lo < hi) {
            int mid = (lo + hi) >> 1;
            if (batch[mid] < target) lo = mid + 1; else hi = mid;
        }
        srange[c] = lo;
    }
    __syncthreads();
    int ns = srange[0], ne = srange[1];
    float m = -3.402823466e+38f;
    for (int n = ns; n < ne; n++)
        m = fmaxf(m, g_hA[(size_t)n * 64 + c]);
    t0[c] = m;
    __syncthreads();
    float s = 0.f;
    #pragma unroll 8
    for (int k = 0; k < 64; k++) s += t0[k] * W1[k * 64 + c];
    t1[c] = fmaxf(s + b1[c], 0.f);
    __syncthreads();
    float o = 0.f;
    #pragma unroll 8
    for (int k = 0; k < 64; k++) o += t1[k] * W2[k * 64 + c];
    out[g * 64 + c] = o + b2[c];
}

// ---------------- launch ----------------
extern "C" void kernel_launch(void* const* d_in, const int* in_sizes, int n_in,
                              void* d_out, int out_size) {
    const float* x     = (const float*)d_in[0];
    const int*   ei    = (const int*)  d_in[1];
    const float* ea    = (const float*)d_in[2];
    const int*   batch = (const int*)  d_in[3];
    const float* W_gcn = (const float*)d_in[4];
    const float* b_gcn = (const float*)d_in[5];
    const float* W1    = (const float*)d_in[6];
    const float* We1   = (const float*)d_in[7];
    const float* as1   = (const float*)d_in[8];
    const float* ad1   = (const float*)d_in[9];
    const float* ae1   = (const float*)d_in[10];
    const float* b1    = (const float*)d_in[11];
    const float* W2    = (const float*)d_in[12];
    const float* We2   = (const float*)d_in[13];
    const float* as2   = (const float*)d_in[14];
    const float* ad2   = (const float*)d_in[15];
    const float* ae2   = (const float*)d_in[16];
    const float* b2    = (const float*)d_in[17];
    const float* Wf1   = (const float*)d_in[18];
    const float* bf1   = (const float*)d_in[19];
    const float* Wf2   = (const float*)d_in[20];
    const float* bf2   = (const float*)d_in[21];
    float* out = (float*)d_out;

    const int* src = ei;
    const int* dst = ei + EE;

    const int TB = 256;
    const int gGemm = (NN + 63) / 64;
    const int gNode = (NN + 7) / 8;

    cudaStream_t s2;
    cudaEvent_t evScan, evB;
    cudaStreamCreateWithFlags(&s2, cudaStreamNonBlocking);
    cudaEventCreateWithFlags(&evScan, cudaEventDisableTiming);
    cudaEventCreateWithFlags(&evB, cudaEventDisableTiming);

    // CSR build on main; GCN GEMM (needs dinv from scan) on side, hidden under scatter
    k_cnt<<<(EE / 4 + TB - 1) / TB, TB>>>((const int4*)dst, We1, ae1, We2, ae2);
    k_scan<<<SCAN_G, SCAN_B>>>();
    cudaEventRecord(evScan, 0);
    cudaStreamWaitEvent(s2, evScan, 0);
    k_gemm<128, 0, 1><<<gGemm, TB, 0, s2>>>(x, W_gcn, nullptr, nullptr, 0);
    cudaEventRecord(evB, s2);
    k_scatter<<<(EE / 4 + TB - 1) / TB, TB>>>(ea, src, dst);
    cudaStreamWaitEvent(0, evB, 0);

    // layers (sequential, full-grid)
    k_gcn_node<<<gNode, TB>>>(b_gcn);

    k_gemm<64, 1, 0><<<gGemm, TB>>>(nullptr, W1, as1, ad1, 1);
    k_gat_node<1, 0><<<gNode, TB>>>(b1);

    k_gemm<64, 1, 0><<<gGemm, TB>>>(nullptr, W2, as2, ad2, 1);
    k_gat_node<2, 1><<<gNode, TB>>>(b2);

    // head
    k_fc<<<GG, 64>>>(batch, Wf1, bf1, Wf2, bf2, out);

    cudaStreamDestroy(s2);
    cudaEventDestroy(evScan);
    cudaEventDestroy(evB);
}